// round 13
// baseline (speedup 1.0000x reference)
#include <cuda_runtime.h>
#include <cuda_bf16.h>
#include <math.h>
#include <stdint.h>

#define Bz   64
#define Sz   32
#define NF   196
#define NP   64
#define ENC  512
#define BENC 768
#define Az   512
#define Dz   512
#define Ez   512
#define Vz   30000
#define G4   2048
#define KP   1792        // packed gates K: ctx 512 | pctx 768 | h 512
#define VPAD 30208
#define NBLK 128
#define LT   512

#define OFF_ALPHA  61440000u
#define OFF_PA     61841408u

// ---------------- scratch ----------------
__device__ float g_u_feat[Bz * NF * Az];
__device__ float g_u_art [Bz * NP * Az];
__device__ float g_h[Bz * Dz], g_c[Bz * Dz];
__device__ float g_gparts8[8 * Bz * G4];         // per-ksplit partial gates
__device__ float g_wah[2 * Bz * Az];
__device__ float g_gemb[(size_t)Bz * Sz * G4];
__device__ float g_zbias[G4];

__device__ __nv_bfloat16 g_fhi[Bz * NF * ENC],  g_flo[Bz * NF * ENC];
__device__ __nv_bfloat16 g_arhi[Bz * NP * BENC], g_arlo[Bz * NP * BENC];
__device__ __nv_bfloat16 g_w1hi[Az * ENC],  g_w1lo[Az * ENC];
__device__ __nv_bfloat16 g_w2hi[Az * BENC], g_w2lo[Az * BENC];
__device__ __nv_bfloat16 g_whi[(size_t)VPAD * Dz], g_wlo[(size_t)VPAD * Dz];
__device__ __nv_bfloat16 g_ahi[Sz * Bz * Dz], g_alo[Sz * Bz * Dz];
__device__ __nv_bfloat16 g_ehi[Bz * Sz * Ez], g_elo[Bz * Sz * Ez];
__device__ __nv_bfloat16 g_wsehi[G4 * 512], g_wselo[G4 * 512];
__device__ __nv_bfloat16 g_wghi[(size_t)G4 * KP], g_wglo[(size_t)G4 * KP];   // packed gates W
__device__ __nv_bfloat16 g_xhi[Bz * KP], g_xlo[Bz * KP];                      // [ctx|pctx|h] splits

__device__ unsigned g_cnt;
__device__ volatile unsigned g_gen;

__device__ __forceinline__ float wred(float v) {
#pragma unroll
    for (int o = 16; o; o >>= 1) v += __shfl_xor_sync(0xffffffffu, v, o);
    return v;
}
__device__ __forceinline__ float sigm(float x) { return 1.f / (1.f + expf(-x)); }
__device__ __forceinline__ float tanha(float x) {
    float y; asm("tanh.approx.f32 %0, %1;" : "=f"(y) : "f"(x)); return y;
}
__device__ __forceinline__ uint32_t smem_u32(const void* p) {
    uint32_t a;
    asm("{ .reg .u64 t; cvta.to.shared.u64 t, %1; cvt.u32.u64 %0, t; }" : "=r"(a) : "l"(p));
    return a;
}
__device__ __forceinline__ void mma16816(float* c, uint32_t a0, uint32_t a1, uint32_t a2,
                                         uint32_t a3, uint32_t b0, uint32_t b1) {
    asm("mma.sync.aligned.m16n8k16.row.col.f32.bf16.bf16.f32 "
        "{%0,%1,%2,%3}, {%4,%5,%6,%7}, {%8,%9}, {%0,%1,%2,%3};"
        : "+f"(c[0]), "+f"(c[1]), "+f"(c[2]), "+f"(c[3])
        : "r"(a0), "r"(a1), "r"(a2), "r"(a3), "r"(b0), "r"(b1));
}
__device__ __forceinline__ void ldsm4(uint32_t& r0, uint32_t& r1, uint32_t& r2, uint32_t& r3,
                                      uint32_t addr) {
    asm volatile("ldmatrix.sync.aligned.m8n8.x4.shared.b16 {%0,%1,%2,%3}, [%4];"
                 : "=r"(r0), "=r"(r1), "=r"(r2), "=r"(r3) : "r"(addr));
}
__device__ __forceinline__ uint32_t swz(int r, int slot) {
    return (uint32_t)(r * 64 + ((slot ^ ((r >> 1) & 3)) << 4));
}
__device__ __forceinline__ void cpa16(uint32_t dst, const void* src) {
    asm volatile("cp.async.cg.shared.global [%0], [%1], 16;" :: "r"(dst), "l"(src));
}
__device__ __forceinline__ void split_store(__nv_bfloat16* hi, __nv_bfloat16* lo,
                                            size_t idx, float v) {
    __nv_bfloat16 h = __float2bfloat16(v);
    hi[idx] = h;
    lo[idx] = __float2bfloat16(v - __bfloat162float(h));
}

__device__ __forceinline__ void gbar() {
    __threadfence();
    __syncthreads();
    if (threadIdx.x == 0) {
        unsigned gen = g_gen;
        if (atomicAdd(&g_cnt, 1u) == NBLK - 1) {
            g_cnt = 0;
            __threadfence();
            g_gen = gen + 1;
        } else {
            while (g_gen == gen) {}
        }
    }
    __syncthreads();
}

// ---------------- prologue ----------------
__device__ __forceinline__ void conv_range(const float* __restrict__ src,
                                           __nv_bfloat16* __restrict__ hi,
                                           __nv_bfloat16* __restrict__ lo,
                                           int n_src, int relblk) {
    int i = (relblk * 256 + threadIdx.x) * 4;
    float4 v = make_float4(0.f, 0.f, 0.f, 0.f);
    if (i < n_src) v = *(const float4*)(src + i);
    __nv_bfloat16 h0 = __float2bfloat16(v.x), h1 = __float2bfloat16(v.y);
    __nv_bfloat16 h2 = __float2bfloat16(v.z), h3 = __float2bfloat16(v.w);
    ((__nv_bfloat162*)(hi + i))[0] = __halves2bfloat162(h0, h1);
    ((__nv_bfloat162*)(hi + i))[1] = __halves2bfloat162(h2, h3);
    ((__nv_bfloat162*)(lo + i))[0] = __halves2bfloat162(
        __float2bfloat16(v.x - __bfloat162float(h0)), __float2bfloat16(v.y - __bfloat162float(h1)));
    ((__nv_bfloat162*)(lo + i))[1] = __halves2bfloat162(
        __float2bfloat16(v.z - __bfloat162float(h2)), __float2bfloat16(v.w - __bfloat162float(h3)));
}

#define PB_EMBED  64
#define PB_CF     2112
#define PB_CAR    8384
#define PB_CW1    11456
#define PB_CW2    11712
#define PB_CWIH   12096
#define PB_CWG    13120
#define PB_CWF    16704
#define PB_TOTAL  31704

__global__ void prologue(const float* __restrict__ features, const float* __restrict__ articles,
                         const float* __restrict__ emb, const int* __restrict__ captions,
                         const float* __restrict__ ihw, const float* __restrict__ ihb,
                         const float* __restrict__ icw, const float* __restrict__ icb,
                         const float* __restrict__ attUw, const float* __restrict__ paUw,
                         const float* __restrict__ w_ih, const float* __restrict__ w_hh,
                         const float* __restrict__ fcnw) {
    int blk = blockIdx.x, tid = threadIdx.x;
    if (blk < PB_EMBED) {
        __shared__ float x[1280];
        int b = blk, lane = tid & 31, wid = tid >> 5;
        for (int k = tid; k < ENC; k += 256) {
            float s = 0.f;
            const float* p = features + (size_t)b * NF * ENC + k;
            for (int n = 0; n < NF; n++) s += p[n * ENC];
            x[k] = s * (1.f / NF);
        }
        for (int k = tid; k < BENC; k += 256) {
            float s = 0.f;
            const float* p = articles + (size_t)b * NP * BENC + k;
            for (int n = 0; n < NP; n++) s += p[n * BENC];
            x[ENC + k] = s * (1.f / NP);
        }
        __syncthreads();
        for (int d = wid; d < Dz; d += 8) {
            float sh = 0.f, sc = 0.f;
            const float* hr = ihw + (size_t)d * 1280;
            const float* cr = icw + (size_t)d * 1280;
            for (int k = lane; k < 1280; k += 32) { float xv = x[k]; sh += hr[k] * xv; sc += cr[k] * xv; }
#pragma unroll
            for (int o = 16; o; o >>= 1) {
                sh += __shfl_xor_sync(0xffffffffu, sh, o);
                sc += __shfl_xor_sync(0xffffffffu, sc, o);
            }
            if (!lane) {
                float h0 = sh + ihb[d];
                g_h[b * Dz + d] = h0;
                g_c[b * Dz + d] = sc + icb[d];
                split_store(g_xhi, g_xlo, (size_t)b * KP + 1280 + d, h0);
            }
        }
    } else if (blk < PB_CF) {
        int bs = blk - PB_EMBED;
        int cap = captions[bs];
        const float* e = emb + (size_t)cap * Ez;
        for (int k = tid; k < Ez; k += 256)
            split_store(g_ehi, g_elo, (size_t)bs * Ez + k, e[k]);
    } else if (blk < PB_CAR) {
        conv_range(features, g_fhi, g_flo, Bz * NF * ENC, blk - PB_CF);
    } else if (blk < PB_CW1) {
        conv_range(articles, g_arhi, g_arlo, Bz * NP * BENC, blk - PB_CAR);
    } else if (blk < PB_CW2) {
        conv_range(attUw, g_w1hi, g_w1lo, Az * ENC, blk - PB_CW1);
    } else if (blk < PB_CWIH) {
        conv_range(paUw, g_w2hi, g_w2lo, Az * BENC, blk - PB_CW2);
    } else if (blk < PB_CWG) {
        // packed w_ih[:, :512] (emb part for precomputed gemb GEMM)
        int i = ((blk - PB_CWIH) * 256 + tid) * 4;
        int row = i >> 9, col = i & 511;
        float4 v = *(const float4*)(w_ih + (size_t)row * 1792 + col);
        __nv_bfloat16 h0 = __float2bfloat16(v.x), h1 = __float2bfloat16(v.y);
        __nv_bfloat16 h2 = __float2bfloat16(v.z), h3 = __float2bfloat16(v.w);
        ((__nv_bfloat162*)(g_wsehi + i))[0] = __halves2bfloat162(h0, h1);
        ((__nv_bfloat162*)(g_wsehi + i))[1] = __halves2bfloat162(h2, h3);
        ((__nv_bfloat162*)(g_wselo + i))[0] = __halves2bfloat162(
            __float2bfloat16(v.x - __bfloat162float(h0)), __float2bfloat16(v.y - __bfloat162float(h1)));
        ((__nv_bfloat162*)(g_wselo + i))[1] = __halves2bfloat162(
            __float2bfloat16(v.z - __bfloat162float(h2)), __float2bfloat16(v.w - __bfloat162float(h3)));
    } else if (blk < PB_CWF) {
        // packed gates W: [ctx | pctx | h] = w_ih[:,512:1792] | w_hh
        int i = ((blk - PB_CWG) * 256 + tid) * 4;
        int j = i / KP, col = i % KP;
        const float* src = (col < 1280) ? (w_ih + (size_t)j * 1792 + 512 + col)
                                        : (w_hh + (size_t)j * 512 + (col - 1280));
        float4 v = *(const float4*)src;
        __nv_bfloat16 h0 = __float2bfloat16(v.x), h1 = __float2bfloat16(v.y);
        __nv_bfloat16 h2 = __float2bfloat16(v.z), h3 = __float2bfloat16(v.w);
        ((__nv_bfloat162*)(g_wghi + i))[0] = __halves2bfloat162(h0, h1);
        ((__nv_bfloat162*)(g_wghi + i))[1] = __halves2bfloat162(h2, h3);
        ((__nv_bfloat162*)(g_wglo + i))[0] = __halves2bfloat162(
            __float2bfloat16(v.x - __bfloat162float(h0)), __float2bfloat16(v.y - __bfloat162float(h1)));
        ((__nv_bfloat162*)(g_wglo + i))[1] = __halves2bfloat162(
            __float2bfloat16(v.z - __bfloat162float(h2)), __float2bfloat16(v.w - __bfloat162float(h3)));
    } else {
        conv_range(fcnw, g_whi, g_wlo, Vz * Dz, blk - PB_CWF);
    }
}

// -------- split-bf16 mma.sync GEMM tile (ldmatrix feed) --------
__device__ __forceinline__ void gemm_tile(
        const __nv_bfloat16* __restrict__ Ahi, const __nv_bfloat16* __restrict__ Alo,
        const __nv_bfloat16* __restrict__ Whi, const __nv_bfloat16* __restrict__ Wlo,
        const float* __restrict__ bias, float* __restrict__ C, int N, int K,
        int m0, int n0, bool perm) {
    __shared__ __align__(16) char smA[2][8192];
    __shared__ __align__(16) char smW[2][8192];
    const int tid = threadIdx.x, lane = tid & 31, wid = tid >> 5;
    const int wm = wid & 1, wn = wid >> 1;
    const int lr4 = lane >> 2, lw = lane & 3;
    const int t8 = lane >> 3, rw = lane & 7;
    const int kc = K >> 5, nch = 3 * kc;
    const int r1 = tid >> 2, cA = tid & 3;
    const uint32_t so1 = swz(r1, cA), so2 = swz(r1 + 64, cA);
    const uint32_t sa[2] = { smem_u32(smA[0]), smem_u32(smA[1]) };
    const uint32_t sb[2] = { smem_u32(smW[0]), smem_u32(smW[1]) };
    float acc[4][4][4] = {};

#define ISSUE(cc, st) do {                                                     \
        int part = ((cc) >= 2 * kc) ? 2 : ((cc) >= kc ? 1 : 0);                \
        int kk = ((cc) - part * kc) << 5;                                      \
        const __nv_bfloat16* As = (part == 1) ? Alo : Ahi;                     \
        const __nv_bfloat16* Ws = (part == 2) ? Wlo : Whi;                     \
        cpa16(sa[st] + so1, As + (size_t)(m0 + r1) * K + kk + cA * 8);         \
        cpa16(sa[st] + so2, As + (size_t)(m0 + r1 + 64) * K + kk + cA * 8);    \
        cpa16(sb[st] + so1, Ws + (size_t)(n0 + r1) * K + kk + cA * 8);         \
        cpa16(sb[st] + so2, Ws + (size_t)(n0 + r1 + 64) * K + kk + cA * 8);    \
        asm volatile("cp.async.commit_group;" ::: "memory");                   \
    } while (0)

    ISSUE(0, 0);
    for (int cc = 0; cc < nch; cc++) {
        const int st = cc & 1;
        if (cc + 1 < nch) {
            ISSUE(cc + 1, st ^ 1);
            asm volatile("cp.async.wait_group 1;" ::: "memory");
        } else {
            asm volatile("cp.async.wait_group 0;" ::: "memory");
        }
        __syncthreads();
        const uint32_t saSt = sa[st], sbSt = sb[st];
#pragma unroll
        for (int ks = 0; ks < 2; ks++) {
            uint32_t bf[4][2];
#pragma unroll
            for (int nip = 0; nip < 2; nip++) {
                uint32_t r0, r1b, r2, r3;
                ldsm4(r0, r1b, r2, r3,
                      sbSt + swz(wn * 32 + nip * 16 + ((t8 >> 1) << 3) + rw, 2 * ks + (t8 & 1)));
                bf[nip * 2][0] = r0; bf[nip * 2][1] = r1b;
                bf[nip * 2 + 1][0] = r2; bf[nip * 2 + 1][1] = r3;
            }
#pragma unroll
            for (int mi = 0; mi < 4; mi++) {
                uint32_t a0, a1, a2, a3;
                ldsm4(a0, a1, a2, a3,
                      saSt + swz(wm * 64 + mi * 16 + ((t8 & 1) << 3) + rw, 2 * ks + (t8 >> 1)));
#pragma unroll
                for (int ni = 0; ni < 4; ni++)
                    mma16816(acc[mi][ni], a0, a1, a2, a3, bf[ni][0], bf[ni][1]);
            }
        }
        __syncthreads();
    }
#undef ISSUE
#pragma unroll
    for (int mi = 0; mi < 4; mi++) {
#pragma unroll
        for (int ni = 0; ni < 4; ni++) {
            int m = m0 + wm * 64 + mi * 16 + lr4;
            int n = n0 + wn * 32 + ni * 8 + lw * 2;
            if (n < N) {
                float bx = bias[n], by = bias[n + 1];
                size_t row0 = perm ? (size_t)((m & 63) * Sz + (m >> 6)) * N : (size_t)m * N;
                size_t row1 = perm ? (size_t)(((m + 8) & 63) * Sz + ((m + 8) >> 6)) * N
                                   : (size_t)(m + 8) * N;
                *(float2*)(C + row0 + n) = make_float2(acc[mi][ni][0] + bx, acc[mi][ni][1] + by);
                *(float2*)(C + row1 + n) = make_float2(acc[mi][ni][2] + bx, acc[mi][ni][3] + by);
            }
        }
    }
}

__global__ void __launch_bounds__(256)
gemm3(const float* __restrict__ attUb, const float* __restrict__ paUb) {
    int y = blockIdx.y, x = blockIdx.x;
    if (y < 98) {
        if (x >= 4) return;
        gemm_tile(g_fhi, g_flo, g_w1hi, g_w1lo, attUb, g_u_feat, Az, ENC, y * 128, x * 128, false);
    } else if (y < 130) {
        if (x >= 4) return;
        gemm_tile(g_arhi, g_arlo, g_w2hi, g_w2lo, paUb, g_u_art, Az, BENC, (y - 98) * 128, x * 128, false);
    } else {
        gemm_tile(g_ehi, g_elo, g_wsehi, g_wselo, g_zbias, g_gemb, G4, 512, (y - 130) * 128, x * 128, false);
    }
}

__global__ void __launch_bounds__(256)
gemm_fcn(const float* __restrict__ bias, float* __restrict__ C) {
    gemm_tile(g_ahi, g_alo, g_whi, g_wlo, bias, C, Vz, Dz,
              blockIdx.y * 128, blockIdx.x * 128, true);
}

// ---------------- persistent loop ----------------
__device__ __forceinline__ void attend_p(float* sh, const float* __restrict__ F,
                                         const float* __restrict__ u,
                                         const float* __restrict__ Aw, float Ab,
                                         int type, int b, int Nn, int Kd, int xoff,
                                         float* __restrict__ outp) {
    const int tid = threadIdx.x, lane = tid & 31, wid = tid >> 5;
    float* wahs = sh;
    float* aws  = sh + 512;
    float* sc   = sh + 1024;
    float* red  = sh + 1232;
    float* sm   = sh + 1248;

    wahs[tid] = g_wah[(size_t)(type * Bz + b) * Az + tid];
    aws[tid] = Aw[tid];
    __syncthreads();

    const float4* w4 = (const float4*)wahs;
    const float4* a4p = (const float4*)aws;
    for (int n = wid; n < Nn; n += 16) {
        const float4* ur4 = (const float4*)(u + (size_t)n * Az);
        float s = 0.f;
#pragma unroll
        for (int q = 0; q < 4; q++) {
            int idx = lane + q * 32;
            float4 uu = ur4[idx];
            float4 ww = w4[idx];
            float4 aa = a4p[idx];
            s += tanha(uu.x + ww.x) * aa.x + tanha(uu.y + ww.y) * aa.y +
                 tanha(uu.z + ww.z) * aa.z + tanha(uu.w + ww.w) * aa.w;
        }
        s = wred(s);
        if (!lane) sc[n] = s + Ab;
    }
    __syncthreads();

    float m = -1e30f;
    for (int n = tid; n < Nn; n += LT) m = fmaxf(m, sc[n]);
#pragma unroll
    for (int o = 16; o; o >>= 1) m = fmaxf(m, __shfl_xor_sync(0xffffffffu, m, o));
    if (!lane) red[wid] = m;
    __syncthreads();
    if (tid == 0) {
        float mm = red[0];
        for (int i = 1; i < 16; i++) mm = fmaxf(mm, red[i]);
        sm[0] = mm;
    }
    __syncthreads();
    float e = 0.f;
    for (int n = tid; n < Nn; n += LT) { float ex = expf(sc[n] - sm[0]); sc[n] = ex; e += ex; }
    e = wred(e);
    if (!lane) red[wid] = e;
    __syncthreads();
    if (tid == 0) {
        float ss = 0.f;
        for (int i = 0; i < 16; i++) ss += red[i];
        sm[1] = ss;
    }
    __syncthreads();
    const float inv = 1.f / sm[1];
    for (int n = tid; n < Nn; n += LT) { float al = sc[n] * inv; sc[n] = al; outp[n] = al; }
    __syncthreads();

    // ctx: thread owns 4 k's (float4 loads); write split-bf16 into X
    int k4 = tid * 4;
    if (k4 < Kd) {
        float a0 = 0.f, a1 = 0.f, a2 = 0.f, a3 = 0.f;
        const float* Fk = F + k4;
        for (int n = 0; n < Nn; n++) {
            float4 f = *(const float4*)(Fk + (size_t)n * Kd);
            float al = sc[n];
            a0 += al * f.x; a1 += al * f.y; a2 += al * f.z; a3 += al * f.w;
        }
        size_t base = (size_t)b * KP + xoff + k4;
        __nv_bfloat16 h0 = __float2bfloat16(a0), h1 = __float2bfloat16(a1);
        __nv_bfloat16 h2 = __float2bfloat16(a2), h3 = __float2bfloat16(a3);
        ((__nv_bfloat162*)(g_xhi + base))[0] = __halves2bfloat162(h0, h1);
        ((__nv_bfloat162*)(g_xhi + base))[1] = __halves2bfloat162(h2, h3);
        ((__nv_bfloat162*)(g_xlo + base))[0] = __halves2bfloat162(
            __float2bfloat16(a0 - __bfloat162float(h0)), __float2bfloat16(a1 - __bfloat162float(h1)));
        ((__nv_bfloat162*)(g_xlo + base))[1] = __halves2bfloat162(
            __float2bfloat16(a2 - __bfloat162float(h2)), __float2bfloat16(a3 - __bfloat162float(h3)));
    }
}

// tensor-core gates: block = (nt, ks): 64 x 128 tile over K-split of 224 (x3 parts)
__device__ __forceinline__ void gates_mma(float* sh, int nt, int ks) {
    const int tid = threadIdx.x, lane = tid & 31, wid = tid >> 5;
    const int wn = wid & 7, mh = wid >> 3;
    const int lr4 = lane >> 2, lw = lane & 3;
    const int t8 = lane >> 3, rw = lane & 7;
    const int koff = ks * 224;
    // smem: X[2][64x64B] at 0 / 4KB ; W[2][128x64B] at 8KB / 16KB
    char* smem = (char*)sh;
    const uint32_t sx[2] = { smem_u32(smem), smem_u32(smem + 4096) };
    const uint32_t sw[2] = { smem_u32(smem + 8192), smem_u32(smem + 16384) };
    const int xr = tid >> 2, xq = tid & 3;   // X: tid<256 (r 0-63); W: all (r 0-127)
    float acc[2][2][4] = {};

#define GISS(cc, st) do {                                                          \
        int part = (cc) / 7;                                                       \
        int kk = koff + ((cc) % 7) * 32;                                           \
        const __nv_bfloat16* Xs_ = (part == 1) ? g_xlo : g_xhi;                    \
        const __nv_bfloat16* Ws_ = (part == 2) ? g_wglo : g_wghi;                  \
        if (tid < 256) cpa16(sx[st] + swz(xr, xq), Xs_ + (size_t)xr * KP + kk + xq * 8); \
        cpa16(sw[st] + swz(xr & 127, xq), Ws_ + (size_t)(nt * 128 + (xr & 127)) * KP + kk + xq * 8); \
        asm volatile("cp.async.commit_group;" ::: "memory");                       \
    } while (0)

    GISS(0, 0);
    for (int cc = 0; cc < 21; cc++) {
        const int st = cc & 1;
        if (cc + 1 < 21) {
            GISS(cc + 1, st ^ 1);
            asm volatile("cp.async.wait_group 1;" ::: "memory");
        } else {
            asm volatile("cp.async.wait_group 0;" ::: "memory");
        }
        __syncthreads();
        const uint32_t sxSt = sx[st], swSt = sw[st];
#pragma unroll
        for (int ks2 = 0; ks2 < 2; ks2++) {
            uint32_t b0, b1, b2, b3;
            ldsm4(b0, b1, b2, b3,
                  swSt + swz(wn * 16 + ((t8 >> 1) << 3) + rw, 2 * ks2 + (t8 & 1)));
#pragma unroll
            for (int mi = 0; mi < 2; mi++) {
                uint32_t a0, a1, a2, a3;
                ldsm4(a0, a1, a2, a3,
                      sxSt + swz(mh * 32 + mi * 16 + ((t8 & 1) << 3) + rw, 2 * ks2 + (t8 >> 1)));
                mma16816(acc[mi][0], a0, a1, a2, a3, b0, b1);
                mma16816(acc[mi][1], a0, a1, a2, a3, b2, b3);
            }
        }
        __syncthreads();
    }
#undef GISS
#pragma unroll
    for (int mi = 0; mi < 2; mi++) {
#pragma unroll
        for (int ni = 0; ni < 2; ni++) {
            int m = mh * 32 + mi * 16 + lr4;
            int n = nt * 128 + wn * 16 + ni * 8 + lw * 2;
            *(float2*)(g_gparts8 + ((size_t)ks * Bz + m) * G4 + n) =
                make_float2(acc[mi][ni][0], acc[mi][ni][1]);
            *(float2*)(g_gparts8 + ((size_t)ks * Bz + m + 8) * G4 + n) =
                make_float2(acc[mi][ni][2], acc[mi][ni][3]);
        }
    }
}

__global__ void __launch_bounds__(LT)
loop_kernel(const float* __restrict__ features, const float* __restrict__ articles,
            const float* __restrict__ attWw, const float* __restrict__ attWb,
            const float* __restrict__ attAw, const float* __restrict__ attAb,
            const float* __restrict__ paWw, const float* __restrict__ paWb,
            const float* __restrict__ paAw, const float* __restrict__ paAb,
            const float* __restrict__ b_ih, const float* __restrict__ b_hh,
            float* __restrict__ out) {
    __shared__ __align__(16) float sh[6144];   // 24KB
    const int bid = blockIdx.x, tid = threadIdx.x;
    const int lane = tid & 31, wid = tid >> 5;
    const int type = bid >> 6, b = bid & 63;
    const float* Wt = type ? paWw : attWw;
    const float* Wbv = type ? paWb : attWb;

    for (int t = 0; t < Sz; t++) {
        // ---- A: distributed wah (rows [b*8, b*8+8) for all 64 batches)
        {
            const int a0 = b * 8;
            for (int i = tid; i < 1024; i += LT)
                ((float4*)sh)[i] = *(const float4*)(Wt + (size_t)(a0 + (i >> 7)) * Dz + ((i & 127) << 2));
            __syncthreads();
#pragma unroll 1
            for (int ib = 0; ib < 4; ib++) {
                int b2 = wid + ib * 16;
                const float4* hp = (const float4*)(g_h + b2 * Dz);
                float4 h4[4];
#pragma unroll
                for (int q = 0; q < 4; q++) h4[q] = hp[lane + q * 32];
#pragma unroll 1
                for (int r = 0; r < 8; r++) {
                    const float4* wr4 = (const float4*)(sh + r * 512);
                    float s = 0.f;
#pragma unroll
                    for (int q = 0; q < 4; q++) {
                        float4 wv = wr4[lane + q * 32];
                        s += wv.x * h4[q].x + wv.y * h4[q].y + wv.z * h4[q].z + wv.w * h4[q].w;
                    }
                    s = wred(s);
                    if (!lane) g_wah[(size_t)(type * Bz + b2) * Az + a0 + r] = s + Wbv[a0 + r];
                }
            }
        }
        gbar();
        // ---- B: attention; ctx/pctx written as split-bf16 into X
        if (type == 0)
            attend_p(sh, features + (size_t)b * NF * ENC, g_u_feat + (size_t)b * NF * Az,
                     attAw, attAb[0], 0, b, NF, ENC, 0,
                     out + OFF_ALPHA + (size_t)(b * Sz + t) * NF);
        else
            attend_p(sh, articles + (size_t)b * NP * BENC, g_u_art + (size_t)b * NP * Az,
                     paAw, paAb[0], 1, b, NP, BENC, 512,
                     out + OFF_PA + (size_t)(b * Sz + t) * NP);
        gbar();
        // ---- C: tensor-core gates (all 128 blocks; 16 n-tiles x 8 k-splits)
        gates_mma(sh, bid & 15, bid >> 4);
        gbar();
        // ---- D: LSTM pointwise (type0 blocks)
        if (type == 0) {
            int d = tid;
            const float* ge = g_gemb + (size_t)(b * Sz + t) * G4;
            float gi = b_ih[d] + b_hh[d] + ge[d];
            float gf = b_ih[512 + d] + b_hh[512 + d] + ge[512 + d];
            float gg = b_ih[1024 + d] + b_hh[1024 + d] + ge[1024 + d];
            float go = b_ih[1536 + d] + b_hh[1536 + d] + ge[1536 + d];
#pragma unroll
            for (int ks = 0; ks < 8; ks++) {
                const float* gp = g_gparts8 + ((size_t)ks * Bz + b) * G4;
                gi += gp[d]; gf += gp[512 + d]; gg += gp[1024 + d]; go += gp[1536 + d];
            }
            float cp = g_c[b * Dz + d];
            float cn = sigm(gf) * cp + sigm(gi) * tanhf(gg);
            float hn = sigm(go) * tanhf(cn);
            g_c[b * Dz + d] = cn;
            g_h[b * Dz + d] = hn;
            __nv_bfloat16 hh = __float2bfloat16(hn);
            __nv_bfloat16 hl = __float2bfloat16(hn - __bfloat162float(hh));
            size_t idx = ((size_t)t * Bz + b) * Dz + d;
            g_ahi[idx] = hh;
            g_alo[idx] = hl;
            g_xhi[(size_t)b * KP + 1280 + d] = hh;
            g_xlo[(size_t)b * KP + 1280 + d] = hl;
        }
        gbar();
    }
}

// ---------------- launcher: 4 launches; #4 = gemm_fcn (ncu target) ----------------
extern "C" void kernel_launch(void* const* d_in, const int* in_sizes, int n_in,
                              void* d_out, int out_size) {
    const float* features = (const float*)d_in[0];
    const float* articles = (const float*)d_in[1];
    const int*   captions = (const int*)d_in[2];
    const float* emb      = (const float*)d_in[3];
    const float* att_W_w  = (const float*)d_in[4];
    const float* att_W_b  = (const float*)d_in[5];
    const float* att_U_w  = (const float*)d_in[6];
    const float* att_U_b  = (const float*)d_in[7];
    const float* att_A_w  = (const float*)d_in[8];
    const float* att_A_b  = (const float*)d_in[9];
    const float* pa_W_w   = (const float*)d_in[10];
    const float* pa_W_b   = (const float*)d_in[11];
    const float* pa_U_w   = (const float*)d_in[12];
    const float* pa_U_b   = (const float*)d_in[13];
    const float* pa_A_w   = (const float*)d_in[14];
    const float* pa_A_b   = (const float*)d_in[15];
    const float* init_h_w = (const float*)d_in[16];
    const float* init_h_b = (const float*)d_in[17];
    const float* init_c_w = (const float*)d_in[18];
    const float* init_c_b = (const float*)d_in[19];
    const float* lstm_w_ih = (const float*)d_in[20];
    const float* lstm_w_hh = (const float*)d_in[21];
    const float* lstm_b_ih = (const float*)d_in[22];
    const float* lstm_b_hh = (const float*)d_in[23];
    const float* fcn_w    = (const float*)d_in[24];
    const float* fcn_b    = (const float*)d_in[25];
    float* out = (float*)d_out;

    prologue<<<PB_TOTAL, 256>>>(features, articles, emb, captions,
                                init_h_w, init_h_b, init_c_w, init_c_b,
                                att_U_w, pa_U_w, lstm_w_ih, lstm_w_hh, fcn_w);
    gemm3<<<dim3(16, 146), 256>>>(att_U_b, pa_U_b);
    loop_kernel<<<NBLK, LT>>>(features, articles,
                              att_W_w, att_W_b, att_A_w, att_A_b,
                              pa_W_w, pa_W_b, pa_A_w, pa_A_b,
                              lstm_b_ih, lstm_b_hh, out);
    gemm_fcn<<<dim3(236, 16), 256>>>(fcn_b, out);
}

// round 14
// speedup vs baseline: 1.0123x; 1.0123x over previous
#include <cuda_runtime.h>
#include <cuda_bf16.h>
#include <math.h>
#include <stdint.h>

#define Bz   64
#define Sz   32
#define NF   196
#define NP   64
#define ENC  512
#define BENC 768
#define Az   512
#define Dz   512
#define Ez   512
#define Vz   30000
#define G4   2048
#define KP   1792        // packed gates K: ctx 512 | pctx 768 | h 512
#define VPAD 30208
#define NBLK 128
#define LT   512

#define OFF_ALPHA  61440000u
#define OFF_PA     61841408u

// ---------------- scratch ----------------
__device__ float g_u_feat[Bz * NF * Az];
__device__ float g_u_art [Bz * NP * Az];
__device__ float g_h[Bz * Dz], g_c[Bz * Dz];
__device__ float g_gparts8[8 * Bz * G4];         // per-ksplit partial gates
__device__ float g_wah[2 * Bz * Az];
__device__ float g_gemb[(size_t)Bz * Sz * G4];
__device__ float g_zbias[G4];

__device__ __nv_bfloat16 g_fhi[Bz * NF * ENC],  g_flo[Bz * NF * ENC];
__device__ __nv_bfloat16 g_arhi[Bz * NP * BENC], g_arlo[Bz * NP * BENC];
__device__ __nv_bfloat16 g_w1hi[Az * ENC],  g_w1lo[Az * ENC];
__device__ __nv_bfloat16 g_w2hi[Az * BENC], g_w2lo[Az * BENC];
__device__ __nv_bfloat16 g_whi[(size_t)VPAD * Dz], g_wlo[(size_t)VPAD * Dz];
__device__ __nv_bfloat16 g_ahi[Sz * Bz * Dz], g_alo[Sz * Bz * Dz];
__device__ __nv_bfloat16 g_ehi[Bz * Sz * Ez], g_elo[Bz * Sz * Ez];
__device__ __nv_bfloat16 g_wsehi[G4 * 512], g_wselo[G4 * 512];
__device__ __nv_bfloat16 g_wghi[(size_t)G4 * KP], g_wglo[(size_t)G4 * KP];   // packed gates W
__device__ __nv_bfloat16 g_xhi[Bz * KP], g_xlo[Bz * KP];                      // [ctx|pctx|h] splits

__device__ unsigned g_cnt;
__device__ volatile unsigned g_gen;

__device__ __forceinline__ float wred(float v) {
#pragma unroll
    for (int o = 16; o; o >>= 1) v += __shfl_xor_sync(0xffffffffu, v, o);
    return v;
}
__device__ __forceinline__ float sigm(float x) { return 1.f / (1.f + expf(-x)); }
__device__ __forceinline__ float tanha(float x) {
    float y; asm("tanh.approx.f32 %0, %1;" : "=f"(y) : "f"(x)); return y;
}
__device__ __forceinline__ uint32_t smem_u32(const void* p) {
    uint32_t a;
    asm("{ .reg .u64 t; cvta.to.shared.u64 t, %1; cvt.u32.u64 %0, t; }" : "=r"(a) : "l"(p));
    return a;
}
__device__ __forceinline__ void mma16816(float* c, uint32_t a0, uint32_t a1, uint32_t a2,
                                         uint32_t a3, uint32_t b0, uint32_t b1) {
    asm("mma.sync.aligned.m16n8k16.row.col.f32.bf16.bf16.f32 "
        "{%0,%1,%2,%3}, {%4,%5,%6,%7}, {%8,%9}, {%0,%1,%2,%3};"
        : "+f"(c[0]), "+f"(c[1]), "+f"(c[2]), "+f"(c[3])
        : "r"(a0), "r"(a1), "r"(a2), "r"(a3), "r"(b0), "r"(b1));
}
__device__ __forceinline__ void ldsm4(uint32_t& r0, uint32_t& r1, uint32_t& r2, uint32_t& r3,
                                      uint32_t addr) {
    asm volatile("ldmatrix.sync.aligned.m8n8.x4.shared.b16 {%0,%1,%2,%3}, [%4];"
                 : "=r"(r0), "=r"(r1), "=r"(r2), "=r"(r3) : "r"(addr));
}
__device__ __forceinline__ uint32_t swz(int r, int slot) {
    return (uint32_t)(r * 64 + ((slot ^ ((r >> 1) & 3)) << 4));
}
__device__ __forceinline__ void cpa16(uint32_t dst, const void* src) {
    asm volatile("cp.async.cg.shared.global [%0], [%1], 16;" :: "r"(dst), "l"(src));
}
__device__ __forceinline__ void split_store(__nv_bfloat16* hi, __nv_bfloat16* lo,
                                            size_t idx, float v) {
    __nv_bfloat16 h = __float2bfloat16(v);
    hi[idx] = h;
    lo[idx] = __float2bfloat16(v - __bfloat162float(h));
}

__device__ __forceinline__ void gbar() {
    __threadfence();
    __syncthreads();
    if (threadIdx.x == 0) {
        unsigned gen = g_gen;
        if (atomicAdd(&g_cnt, 1u) == NBLK - 1) {
            g_cnt = 0;
            __threadfence();
            g_gen = gen + 1;
        } else {
            while (g_gen == gen) {}
        }
    }
    __syncthreads();
}

// ---------------- prologue ----------------
__device__ __forceinline__ void conv_range(const float* __restrict__ src,
                                           __nv_bfloat16* __restrict__ hi,
                                           __nv_bfloat16* __restrict__ lo,
                                           int n_src, int relblk) {
    int i = (relblk * 256 + threadIdx.x) * 4;
    float4 v = make_float4(0.f, 0.f, 0.f, 0.f);
    if (i < n_src) v = *(const float4*)(src + i);
    __nv_bfloat16 h0 = __float2bfloat16(v.x), h1 = __float2bfloat16(v.y);
    __nv_bfloat16 h2 = __float2bfloat16(v.z), h3 = __float2bfloat16(v.w);
    ((__nv_bfloat162*)(hi + i))[0] = __halves2bfloat162(h0, h1);
    ((__nv_bfloat162*)(hi + i))[1] = __halves2bfloat162(h2, h3);
    ((__nv_bfloat162*)(lo + i))[0] = __halves2bfloat162(
        __float2bfloat16(v.x - __bfloat162float(h0)), __float2bfloat16(v.y - __bfloat162float(h1)));
    ((__nv_bfloat162*)(lo + i))[1] = __halves2bfloat162(
        __float2bfloat16(v.z - __bfloat162float(h2)), __float2bfloat16(v.w - __bfloat162float(h3)));
}

#define PB_EMBED  64
#define PB_CF     2112
#define PB_CAR    8384
#define PB_CW1    11456
#define PB_CW2    11712
#define PB_CWIH   12096
#define PB_CWG    13120
#define PB_CWF    16704
#define PB_TOTAL  31704

__global__ void prologue(const float* __restrict__ features, const float* __restrict__ articles,
                         const float* __restrict__ emb, const int* __restrict__ captions,
                         const float* __restrict__ ihw, const float* __restrict__ ihb,
                         const float* __restrict__ icw, const float* __restrict__ icb,
                         const float* __restrict__ attUw, const float* __restrict__ paUw,
                         const float* __restrict__ w_ih, const float* __restrict__ w_hh,
                         const float* __restrict__ fcnw) {
    int blk = blockIdx.x, tid = threadIdx.x;
    if (blk < PB_EMBED) {
        __shared__ float x[1280];
        int b = blk, lane = tid & 31, wid = tid >> 5;
        for (int k = tid; k < ENC; k += 256) {
            float s = 0.f;
            const float* p = features + (size_t)b * NF * ENC + k;
            for (int n = 0; n < NF; n++) s += p[n * ENC];
            x[k] = s * (1.f / NF);
        }
        for (int k = tid; k < BENC; k += 256) {
            float s = 0.f;
            const float* p = articles + (size_t)b * NP * BENC + k;
            for (int n = 0; n < NP; n++) s += p[n * BENC];
            x[ENC + k] = s * (1.f / NP);
        }
        __syncthreads();
        for (int d = wid; d < Dz; d += 8) {
            float sh = 0.f, sc = 0.f;
            const float* hr = ihw + (size_t)d * 1280;
            const float* cr = icw + (size_t)d * 1280;
            for (int k = lane; k < 1280; k += 32) { float xv = x[k]; sh += hr[k] * xv; sc += cr[k] * xv; }
#pragma unroll
            for (int o = 16; o; o >>= 1) {
                sh += __shfl_xor_sync(0xffffffffu, sh, o);
                sc += __shfl_xor_sync(0xffffffffu, sc, o);
            }
            if (!lane) {
                float h0 = sh + ihb[d];
                g_h[b * Dz + d] = h0;
                g_c[b * Dz + d] = sc + icb[d];
                split_store(g_xhi, g_xlo, (size_t)b * KP + 1280 + d, h0);
            }
        }
    } else if (blk < PB_CF) {
        int bs = blk - PB_EMBED;
        int cap = captions[bs];
        const float* e = emb + (size_t)cap * Ez;
        for (int k = tid; k < Ez; k += 256)
            split_store(g_ehi, g_elo, (size_t)bs * Ez + k, e[k]);
    } else if (blk < PB_CAR) {
        conv_range(features, g_fhi, g_flo, Bz * NF * ENC, blk - PB_CF);
    } else if (blk < PB_CW1) {
        conv_range(articles, g_arhi, g_arlo, Bz * NP * BENC, blk - PB_CAR);
    } else if (blk < PB_CW2) {
        conv_range(attUw, g_w1hi, g_w1lo, Az * ENC, blk - PB_CW1);
    } else if (blk < PB_CWIH) {
        conv_range(paUw, g_w2hi, g_w2lo, Az * BENC, blk - PB_CW2);
    } else if (blk < PB_CWG) {
        // packed w_ih[:, :512] (emb part for precomputed gemb GEMM)
        int i = ((blk - PB_CWIH) * 256 + tid) * 4;
        int row = i >> 9, col = i & 511;
        float4 v = *(const float4*)(w_ih + (size_t)row * 1792 + col);
        __nv_bfloat16 h0 = __float2bfloat16(v.x), h1 = __float2bfloat16(v.y);
        __nv_bfloat16 h2 = __float2bfloat16(v.z), h3 = __float2bfloat16(v.w);
        ((__nv_bfloat162*)(g_wsehi + i))[0] = __halves2bfloat162(h0, h1);
        ((__nv_bfloat162*)(g_wsehi + i))[1] = __halves2bfloat162(h2, h3);
        ((__nv_bfloat162*)(g_wselo + i))[0] = __halves2bfloat162(
            __float2bfloat16(v.x - __bfloat162float(h0)), __float2bfloat16(v.y - __bfloat162float(h1)));
        ((__nv_bfloat162*)(g_wselo + i))[1] = __halves2bfloat162(
            __float2bfloat16(v.z - __bfloat162float(h2)), __float2bfloat16(v.w - __bfloat162float(h3)));
    } else if (blk < PB_CWF) {
        // packed gates W: [ctx | pctx | h] = w_ih[:,512:1792] | w_hh
        int i = ((blk - PB_CWG) * 256 + tid) * 4;
        int j = i / KP, col = i % KP;
        const float* src = (col < 1280) ? (w_ih + (size_t)j * 1792 + 512 + col)
                                        : (w_hh + (size_t)j * 512 + (col - 1280));
        float4 v = *(const float4*)src;
        __nv_bfloat16 h0 = __float2bfloat16(v.x), h1 = __float2bfloat16(v.y);
        __nv_bfloat16 h2 = __float2bfloat16(v.z), h3 = __float2bfloat16(v.w);
        ((__nv_bfloat162*)(g_wghi + i))[0] = __halves2bfloat162(h0, h1);
        ((__nv_bfloat162*)(g_wghi + i))[1] = __halves2bfloat162(h2, h3);
        ((__nv_bfloat162*)(g_wglo + i))[0] = __halves2bfloat162(
            __float2bfloat16(v.x - __bfloat162float(h0)), __float2bfloat16(v.y - __bfloat162float(h1)));
        ((__nv_bfloat162*)(g_wglo + i))[1] = __halves2bfloat162(
            __float2bfloat16(v.z - __bfloat162float(h2)), __float2bfloat16(v.w - __bfloat162float(h3)));
    } else {
        conv_range(fcnw, g_whi, g_wlo, Vz * Dz, blk - PB_CWF);
    }
}

// -------- split-bf16 mma.sync GEMM tile (ldmatrix feed) --------
__device__ __forceinline__ void gemm_tile(
        const __nv_bfloat16* __restrict__ Ahi, const __nv_bfloat16* __restrict__ Alo,
        const __nv_bfloat16* __restrict__ Whi, const __nv_bfloat16* __restrict__ Wlo,
        const float* __restrict__ bias, float* __restrict__ C, int N, int K,
        int m0, int n0, bool perm) {
    __shared__ __align__(16) char smA[2][8192];
    __shared__ __align__(16) char smW[2][8192];
    const int tid = threadIdx.x, lane = tid & 31, wid = tid >> 5;
    const int wm = wid & 1, wn = wid >> 1;
    const int lr4 = lane >> 2, lw = lane & 3;
    const int t8 = lane >> 3, rw = lane & 7;
    const int kc = K >> 5, nch = 3 * kc;
    const int r1 = tid >> 2, cA = tid & 3;
    const uint32_t so1 = swz(r1, cA), so2 = swz(r1 + 64, cA);
    const uint32_t sa[2] = { smem_u32(smA[0]), smem_u32(smA[1]) };
    const uint32_t sb[2] = { smem_u32(smW[0]), smem_u32(smW[1]) };
    float acc[4][4][4] = {};

#define ISSUE(cc, st) do {                                                     \
        int part = ((cc) >= 2 * kc) ? 2 : ((cc) >= kc ? 1 : 0);                \
        int kk = ((cc) - part * kc) << 5;                                      \
        const __nv_bfloat16* As = (part == 1) ? Alo : Ahi;                     \
        const __nv_bfloat16* Ws = (part == 2) ? Wlo : Whi;                     \
        cpa16(sa[st] + so1, As + (size_t)(m0 + r1) * K + kk + cA * 8);         \
        cpa16(sa[st] + so2, As + (size_t)(m0 + r1 + 64) * K + kk + cA * 8);    \
        cpa16(sb[st] + so1, Ws + (size_t)(n0 + r1) * K + kk + cA * 8);         \
        cpa16(sb[st] + so2, Ws + (size_t)(n0 + r1 + 64) * K + kk + cA * 8);    \
        asm volatile("cp.async.commit_group;" ::: "memory");                   \
    } while (0)

    ISSUE(0, 0);
    for (int cc = 0; cc < nch; cc++) {
        const int st = cc & 1;
        if (cc + 1 < nch) {
            ISSUE(cc + 1, st ^ 1);
            asm volatile("cp.async.wait_group 1;" ::: "memory");
        } else {
            asm volatile("cp.async.wait_group 0;" ::: "memory");
        }
        __syncthreads();
        const uint32_t saSt = sa[st], sbSt = sb[st];
#pragma unroll
        for (int ks = 0; ks < 2; ks++) {
            uint32_t bf[4][2];
#pragma unroll
            for (int nip = 0; nip < 2; nip++) {
                uint32_t r0, r1b, r2, r3;
                ldsm4(r0, r1b, r2, r3,
                      sbSt + swz(wn * 32 + nip * 16 + ((t8 >> 1) << 3) + rw, 2 * ks + (t8 & 1)));
                bf[nip * 2][0] = r0; bf[nip * 2][1] = r1b;
                bf[nip * 2 + 1][0] = r2; bf[nip * 2 + 1][1] = r3;
            }
#pragma unroll
            for (int mi = 0; mi < 4; mi++) {
                uint32_t a0, a1, a2, a3;
                ldsm4(a0, a1, a2, a3,
                      saSt + swz(wm * 64 + mi * 16 + ((t8 & 1) << 3) + rw, 2 * ks + (t8 >> 1)));
#pragma unroll
                for (int ni = 0; ni < 4; ni++)
                    mma16816(acc[mi][ni], a0, a1, a2, a3, bf[ni][0], bf[ni][1]);
            }
        }
        __syncthreads();
    }
#undef ISSUE
#pragma unroll
    for (int mi = 0; mi < 4; mi++) {
#pragma unroll
        for (int ni = 0; ni < 4; ni++) {
            int m = m0 + wm * 64 + mi * 16 + lr4;
            int n = n0 + wn * 32 + ni * 8 + lw * 2;
            if (n < N) {
                float bx = bias[n], by = bias[n + 1];
                size_t row0 = perm ? (size_t)((m & 63) * Sz + (m >> 6)) * N : (size_t)m * N;
                size_t row1 = perm ? (size_t)(((m + 8) & 63) * Sz + ((m + 8) >> 6)) * N
                                   : (size_t)(m + 8) * N;
                *(float2*)(C + row0 + n) = make_float2(acc[mi][ni][0] + bx, acc[mi][ni][1] + by);
                *(float2*)(C + row1 + n) = make_float2(acc[mi][ni][2] + bx, acc[mi][ni][3] + by);
            }
        }
    }
}

__global__ void __launch_bounds__(256)
gemm3(const float* __restrict__ attUb, const float* __restrict__ paUb) {
    int y = blockIdx.y, x = blockIdx.x;
    if (y < 98) {
        if (x >= 4) return;
        gemm_tile(g_fhi, g_flo, g_w1hi, g_w1lo, attUb, g_u_feat, Az, ENC, y * 128, x * 128, false);
    } else if (y < 130) {
        if (x >= 4) return;
        gemm_tile(g_arhi, g_arlo, g_w2hi, g_w2lo, paUb, g_u_art, Az, BENC, (y - 98) * 128, x * 128, false);
    } else {
        gemm_tile(g_ehi, g_elo, g_wsehi, g_wselo, g_zbias, g_gemb, G4, 512, (y - 130) * 128, x * 128, false);
    }
}

__global__ void __launch_bounds__(256)
gemm_fcn(const float* __restrict__ bias, float* __restrict__ C) {
    gemm_tile(g_ahi, g_alo, g_whi, g_wlo, bias, C, Vz, Dz,
              blockIdx.y * 128, blockIdx.x * 128, true);
}

// ---------------- persistent loop ----------------
__device__ __forceinline__ void attend_p(float* sh, const float* __restrict__ F,
                                         const float* __restrict__ u,
                                         const float* __restrict__ Aw, float Ab,
                                         int type, int b, int Nn, int Kd, int xoff,
                                         float* __restrict__ outp) {
    const int tid = threadIdx.x, lane = tid & 31, wid = tid >> 5;
    float* wahs = sh;
    float* aws  = sh + 512;
    float* sc   = sh + 1024;
    float* red  = sh + 1232;
    float* sm   = sh + 1248;

    wahs[tid] = g_wah[(size_t)(type * Bz + b) * Az + tid];
    aws[tid] = Aw[tid];
    __syncthreads();

    const float4* w4 = (const float4*)wahs;
    const float4* a4p = (const float4*)aws;
    for (int n = wid; n < Nn; n += 16) {
        const float4* ur4 = (const float4*)(u + (size_t)n * Az);
        float s = 0.f;
#pragma unroll
        for (int q = 0; q < 4; q++) {
            int idx = lane + q * 32;
            float4 uu = ur4[idx];
            float4 ww = w4[idx];
            float4 aa = a4p[idx];
            s += tanha(uu.x + ww.x) * aa.x + tanha(uu.y + ww.y) * aa.y +
                 tanha(uu.z + ww.z) * aa.z + tanha(uu.w + ww.w) * aa.w;
        }
        s = wred(s);
        if (!lane) sc[n] = s + Ab;
    }
    __syncthreads();

    float m = -1e30f;
    for (int n = tid; n < Nn; n += LT) m = fmaxf(m, sc[n]);
#pragma unroll
    for (int o = 16; o; o >>= 1) m = fmaxf(m, __shfl_xor_sync(0xffffffffu, m, o));
    if (!lane) red[wid] = m;
    __syncthreads();
    if (tid == 0) {
        float mm = red[0];
        for (int i = 1; i < 16; i++) mm = fmaxf(mm, red[i]);
        sm[0] = mm;
    }
    __syncthreads();
    float e = 0.f;
    for (int n = tid; n < Nn; n += LT) { float ex = expf(sc[n] - sm[0]); sc[n] = ex; e += ex; }
    e = wred(e);
    if (!lane) red[wid] = e;
    __syncthreads();
    if (tid == 0) {
        float ss = 0.f;
        for (int i = 0; i < 16; i++) ss += red[i];
        sm[1] = ss;
    }
    __syncthreads();
    const float inv = 1.f / sm[1];
    for (int n = tid; n < Nn; n += LT) { float al = sc[n] * inv; sc[n] = al; outp[n] = al; }
    __syncthreads();

    // ctx: thread owns 4 k's (float4 loads); write split-bf16 into X
    int k4 = tid * 4;
    if (k4 < Kd) {
        float a0 = 0.f, a1 = 0.f, a2 = 0.f, a3 = 0.f;
        const float* Fk = F + k4;
        for (int n = 0; n < Nn; n++) {
            float4 f = *(const float4*)(Fk + (size_t)n * Kd);
            float al = sc[n];
            a0 += al * f.x; a1 += al * f.y; a2 += al * f.z; a3 += al * f.w;
        }
        size_t base = (size_t)b * KP + xoff + k4;
        __nv_bfloat16 h0 = __float2bfloat16(a0), h1 = __float2bfloat16(a1);
        __nv_bfloat16 h2 = __float2bfloat16(a2), h3 = __float2bfloat16(a3);
        ((__nv_bfloat162*)(g_xhi + base))[0] = __halves2bfloat162(h0, h1);
        ((__nv_bfloat162*)(g_xhi + base))[1] = __halves2bfloat162(h2, h3);
        ((__nv_bfloat162*)(g_xlo + base))[0] = __halves2bfloat162(
            __float2bfloat16(a0 - __bfloat162float(h0)), __float2bfloat16(a1 - __bfloat162float(h1)));
        ((__nv_bfloat162*)(g_xlo + base))[1] = __halves2bfloat162(
            __float2bfloat16(a2 - __bfloat162float(h2)), __float2bfloat16(a3 - __bfloat162float(h3)));
    }
}

// tensor-core gates: block = (nt, ks): 64 x 128 tile over K-split of 224 (x3 parts)
__device__ __forceinline__ void gates_mma(float* sh, int nt, int ks) {
    const int tid = threadIdx.x, lane = tid & 31, wid = tid >> 5;
    const int wn = wid & 7, mh = wid >> 3;
    const int lr4 = lane >> 2, lw = lane & 3;
    const int t8 = lane >> 3, rw = lane & 7;
    const int koff = ks * 224;
    // smem: X[2][64x64B] at 0 / 4KB ; W[2][128x64B] at 8KB / 16KB
    char* smem = (char*)sh;
    const uint32_t sx[2] = { smem_u32(smem), smem_u32(smem + 4096) };
    const uint32_t sw[2] = { smem_u32(smem + 8192), smem_u32(smem + 16384) };
    const int xr = tid >> 2, xq = tid & 3;   // X: tid<256 (r 0-63); W: all (r 0-127)
    float acc[2][2][4] = {};

#define GISS(cc, st) do {                                                          \
        int part = (cc) / 7;                                                       \
        int kk = koff + ((cc) % 7) * 32;                                           \
        const __nv_bfloat16* Xs_ = (part == 1) ? g_xlo : g_xhi;                    \
        const __nv_bfloat16* Ws_ = (part == 2) ? g_wglo : g_wghi;                  \
        if (tid < 256) cpa16(sx[st] + swz(xr, xq), Xs_ + (size_t)xr * KP + kk + xq * 8); \
        cpa16(sw[st] + swz(xr & 127, xq), Ws_ + (size_t)(nt * 128 + (xr & 127)) * KP + kk + xq * 8); \
        asm volatile("cp.async.commit_group;" ::: "memory");                       \
    } while (0)

    GISS(0, 0);
    for (int cc = 0; cc < 21; cc++) {
        const int st = cc & 1;
        if (cc + 1 < 21) {
            GISS(cc + 1, st ^ 1);
            asm volatile("cp.async.wait_group 1;" ::: "memory");
        } else {
            asm volatile("cp.async.wait_group 0;" ::: "memory");
        }
        __syncthreads();
        const uint32_t sxSt = sx[st], swSt = sw[st];
#pragma unroll
        for (int ks2 = 0; ks2 < 2; ks2++) {
            uint32_t b0, b1, b2, b3;
            ldsm4(b0, b1, b2, b3,
                  swSt + swz(wn * 16 + ((t8 >> 1) << 3) + rw, 2 * ks2 + (t8 & 1)));
#pragma unroll
            for (int mi = 0; mi < 2; mi++) {
                uint32_t a0, a1, a2, a3;
                ldsm4(a0, a1, a2, a3,
                      sxSt + swz(mh * 32 + mi * 16 + ((t8 & 1) << 3) + rw, 2 * ks2 + (t8 >> 1)));
                mma16816(acc[mi][0], a0, a1, a2, a3, b0, b1);
                mma16816(acc[mi][1], a0, a1, a2, a3, b2, b3);
            }
        }
        __syncthreads();
    }
#undef GISS
#pragma unroll
    for (int mi = 0; mi < 2; mi++) {
#pragma unroll
        for (int ni = 0; ni < 2; ni++) {
            int m = mh * 32 + mi * 16 + lr4;
            int n = nt * 128 + wn * 16 + ni * 8 + lw * 2;
            *(float2*)(g_gparts8 + ((size_t)ks * Bz + m) * G4 + n) =
                make_float2(acc[mi][ni][0], acc[mi][ni][1]);
            *(float2*)(g_gparts8 + ((size_t)ks * Bz + m + 8) * G4 + n) =
                make_float2(acc[mi][ni][2], acc[mi][ni][3]);
        }
    }
}

__global__ void __launch_bounds__(LT)
loop_kernel(const float* __restrict__ features, const float* __restrict__ articles,
            const float* __restrict__ attWw, const float* __restrict__ attWb,
            const float* __restrict__ attAw, const float* __restrict__ attAb,
            const float* __restrict__ paWw, const float* __restrict__ paWb,
            const float* __restrict__ paAw, const float* __restrict__ paAb,
            const float* __restrict__ b_ih, const float* __restrict__ b_hh,
            float* __restrict__ out) {
    __shared__ __align__(16) float sh[6144];   // 24KB
    const int bid = blockIdx.x, tid = threadIdx.x;
    const int lane = tid & 31, wid = tid >> 5;
    const int type = bid >> 6, b = bid & 63;
    const float* Wt = type ? paWw : attWw;
    const float* Wbv = type ? paWb : attWb;

    for (int t = 0; t < Sz; t++) {
        // ---- A: distributed wah (rows [b*8, b*8+8) for all 64 batches)
        {
            const int a0 = b * 8;
            for (int i = tid; i < 1024; i += LT)
                ((float4*)sh)[i] = *(const float4*)(Wt + (size_t)(a0 + (i >> 7)) * Dz + ((i & 127) << 2));
            __syncthreads();
#pragma unroll 1
            for (int ib = 0; ib < 4; ib++) {
                int b2 = wid + ib * 16;
                const float4* hp = (const float4*)(g_h + b2 * Dz);
                float4 h4[4];
#pragma unroll
                for (int q = 0; q < 4; q++) h4[q] = hp[lane + q * 32];
#pragma unroll 1
                for (int r = 0; r < 8; r++) {
                    const float4* wr4 = (const float4*)(sh + r * 512);
                    float s = 0.f;
#pragma unroll
                    for (int q = 0; q < 4; q++) {
                        float4 wv = wr4[lane + q * 32];
                        s += wv.x * h4[q].x + wv.y * h4[q].y + wv.z * h4[q].z + wv.w * h4[q].w;
                    }
                    s = wred(s);
                    if (!lane) g_wah[(size_t)(type * Bz + b2) * Az + a0 + r] = s + Wbv[a0 + r];
                }
            }
        }
        gbar();
        // ---- B: attention; ctx/pctx written as split-bf16 into X
        if (type == 0)
            attend_p(sh, features + (size_t)b * NF * ENC, g_u_feat + (size_t)b * NF * Az,
                     attAw, attAb[0], 0, b, NF, ENC, 0,
                     out + OFF_ALPHA + (size_t)(b * Sz + t) * NF);
        else
            attend_p(sh, articles + (size_t)b * NP * BENC, g_u_art + (size_t)b * NP * Az,
                     paAw, paAb[0], 1, b, NP, BENC, 512,
                     out + OFF_PA + (size_t)(b * Sz + t) * NP);
        gbar();
        // ---- C: tensor-core gates (all 128 blocks; 16 n-tiles x 8 k-splits)
        gates_mma(sh, bid & 15, bid >> 4);
        gbar();
        // ---- D: LSTM pointwise (type0 blocks)
        if (type == 0) {
            int d = tid;
            const float* ge = g_gemb + (size_t)(b * Sz + t) * G4;
            float gi = b_ih[d] + b_hh[d] + ge[d];
            float gf = b_ih[512 + d] + b_hh[512 + d] + ge[512 + d];
            float gg = b_ih[1024 + d] + b_hh[1024 + d] + ge[1024 + d];
            float go = b_ih[1536 + d] + b_hh[1536 + d] + ge[1536 + d];
#pragma unroll
            for (int ks = 0; ks < 8; ks++) {
                const float* gp = g_gparts8 + ((size_t)ks * Bz + b) * G4;
                gi += gp[d]; gf += gp[512 + d]; gg += gp[1024 + d]; go += gp[1536 + d];
            }
            float cp = g_c[b * Dz + d];
            float cn = sigm(gf) * cp + sigm(gi) * tanhf(gg);
            float hn = sigm(go) * tanhf(cn);
            g_c[b * Dz + d] = cn;
            g_h[b * Dz + d] = hn;
            __nv_bfloat16 hh = __float2bfloat16(hn);
            __nv_bfloat16 hl = __float2bfloat16(hn - __bfloat162float(hh));
            size_t idx = ((size_t)t * Bz + b) * Dz + d;
            g_ahi[idx] = hh;
            g_alo[idx] = hl;
            g_xhi[(size_t)b * KP + 1280 + d] = hh;
            g_xlo[(size_t)b * KP + 1280 + d] = hl;
        }
        gbar();
    }
}

// ---------------- launcher: 4 launches; #4 = gemm_fcn (ncu target) ----------------
extern "C" void kernel_launch(void* const* d_in, const int* in_sizes, int n_in,
                              void* d_out, int out_size) {
    const float* features = (const float*)d_in[0];
    const float* articles = (const float*)d_in[1];
    const int*   captions = (const int*)d_in[2];
    const float* emb      = (const float*)d_in[3];
    const float* att_W_w  = (const float*)d_in[4];
    const float* att_W_b  = (const float*)d_in[5];
    const float* att_U_w  = (const float*)d_in[6];
    const float* att_U_b  = (const float*)d_in[7];
    const float* att_A_w  = (const float*)d_in[8];
    const float* att_A_b  = (const float*)d_in[9];
    const float* pa_W_w   = (const float*)d_in[10];
    const float* pa_W_b   = (const float*)d_in[11];
    const float* pa_U_w   = (const float*)d_in[12];
    const float* pa_U_b   = (const float*)d_in[13];
    const float* pa_A_w   = (const float*)d_in[14];
    const float* pa_A_b   = (const float*)d_in[15];
    const float* init_h_w = (const float*)d_in[16];
    const float* init_h_b = (const float*)d_in[17];
    const float* init_c_w = (const float*)d_in[18];
    const float* init_c_b = (const float*)d_in[19];
    const float* lstm_w_ih = (const float*)d_in[20];
    const float* lstm_w_hh = (const float*)d_in[21];
    const float* lstm_b_ih = (const float*)d_in[22];
    const float* lstm_b_hh = (const float*)d_in[23];
    const float* fcn_w    = (const float*)d_in[24];
    const float* fcn_b    = (const float*)d_in[25];
    float* out = (float*)d_out;

    prologue<<<PB_TOTAL, 256>>>(features, articles, emb, captions,
                                init_h_w, init_h_b, init_c_w, init_c_b,
                                att_U_w, pa_U_w, lstm_w_ih, lstm_w_hh, fcn_w);
    gemm3<<<dim3(16, 146), 256>>>(att_U_b, pa_U_b);
    loop_kernel<<<NBLK, LT>>>(features, articles,
                              att_W_w, att_W_b, att_A_w, att_A_b,
                              pa_W_w, pa_W_b, pa_A_w, pa_A_b,
                              lstm_b_ih, lstm_b_hh, out);
    gemm_fcn<<<dim3(236, 16), 256>>>(fcn_b, out);
}

// round 15
// speedup vs baseline: 1.0345x; 1.0219x over previous
#include <cuda_runtime.h>
#include <cuda_bf16.h>
#include <math.h>
#include <stdint.h>

#define Bz   64
#define Sz   32
#define NF   196
#define NP   64
#define ENC  512
#define BENC 768
#define Az   512
#define Dz   512
#define Ez   512
#define Vz   30000
#define G4   2048
#define KP   1792        // packed gates K: ctx 512 | pctx 768 | h 512
#define VPAD 30208
#define NBLK 128
#define LT   512

#define OFF_ALPHA  61440000u
#define OFF_PA     61841408u

// ---------------- scratch ----------------
__device__ float g_u_feat[Bz * NF * Az];
__device__ float g_u_art [Bz * NP * Az];
__device__ float g_h[Bz * Dz], g_c[Bz * Dz];
__device__ float g_gparts8[8 * Bz * G4];         // per-ksplit partial gates
__device__ float g_wah[2 * Bz * Az];
__device__ float g_gemb[(size_t)Bz * Sz * G4];
__device__ float g_zbias[G4];

__device__ __nv_bfloat16 g_fhi[Bz * NF * ENC],  g_flo[Bz * NF * ENC];
__device__ __nv_bfloat16 g_arhi[Bz * NP * BENC], g_arlo[Bz * NP * BENC];
__device__ __nv_bfloat16 g_w1hi[Az * ENC],  g_w1lo[Az * ENC];
__device__ __nv_bfloat16 g_w2hi[Az * BENC], g_w2lo[Az * BENC];
__device__ __nv_bfloat16 g_whi[(size_t)VPAD * Dz], g_wlo[(size_t)VPAD * Dz];
__device__ __nv_bfloat16 g_ahi[Sz * Bz * Dz], g_alo[Sz * Bz * Dz];
__device__ __nv_bfloat16 g_ehi[Bz * Sz * Ez], g_elo[Bz * Sz * Ez];
__device__ __nv_bfloat16 g_wsehi[G4 * 512], g_wselo[G4 * 512];
__device__ __nv_bfloat16 g_wghi[(size_t)G4 * KP], g_wglo[(size_t)G4 * KP];   // packed gates W
__device__ __nv_bfloat16 g_xhi[Bz * KP], g_xlo[Bz * KP];                      // [ctx|pctx|h] splits

__device__ unsigned g_cnt;
__device__ volatile unsigned g_gen;

__device__ __forceinline__ float wred(float v) {
#pragma unroll
    for (int o = 16; o; o >>= 1) v += __shfl_xor_sync(0xffffffffu, v, o);
    return v;
}
__device__ __forceinline__ float sigm(float x) { return 1.f / (1.f + expf(-x)); }
__device__ __forceinline__ float tanha(float x) {
    float y; asm("tanh.approx.f32 %0, %1;" : "=f"(y) : "f"(x)); return y;
}
__device__ __forceinline__ uint32_t smem_u32(const void* p) {
    uint32_t a;
    asm("{ .reg .u64 t; cvta.to.shared.u64 t, %1; cvt.u32.u64 %0, t; }" : "=r"(a) : "l"(p));
    return a;
}
__device__ __forceinline__ void mma16816(float* c, uint32_t a0, uint32_t a1, uint32_t a2,
                                         uint32_t a3, uint32_t b0, uint32_t b1) {
    asm("mma.sync.aligned.m16n8k16.row.col.f32.bf16.bf16.f32 "
        "{%0,%1,%2,%3}, {%4,%5,%6,%7}, {%8,%9}, {%0,%1,%2,%3};"
        : "+f"(c[0]), "+f"(c[1]), "+f"(c[2]), "+f"(c[3])
        : "r"(a0), "r"(a1), "r"(a2), "r"(a3), "r"(b0), "r"(b1));
}
__device__ __forceinline__ void ldsm4(uint32_t& r0, uint32_t& r1, uint32_t& r2, uint32_t& r3,
                                      uint32_t addr) {
    asm volatile("ldmatrix.sync.aligned.m8n8.x4.shared.b16 {%0,%1,%2,%3}, [%4];"
                 : "=r"(r0), "=r"(r1), "=r"(r2), "=r"(r3) : "r"(addr));
}
__device__ __forceinline__ uint32_t swz(int r, int slot) {
    return (uint32_t)(r * 64 + ((slot ^ ((r >> 1) & 3)) << 4));
}
__device__ __forceinline__ void cpa16(uint32_t dst, const void* src) {
    asm volatile("cp.async.cg.shared.global [%0], [%1], 16;" :: "r"(dst), "l"(src));
}
__device__ __forceinline__ void split_store(__nv_bfloat16* hi, __nv_bfloat16* lo,
                                            size_t idx, float v) {
    __nv_bfloat16 h = __float2bfloat16(v);
    hi[idx] = h;
    lo[idx] = __float2bfloat16(v - __bfloat162float(h));
}

__device__ __forceinline__ void gbar() {
    __threadfence();
    __syncthreads();
    if (threadIdx.x == 0) {
        unsigned gen = g_gen;
        if (atomicAdd(&g_cnt, 1u) == NBLK - 1) {
            g_cnt = 0;
            __threadfence();
            g_gen = gen + 1;
        } else {
            while (g_gen == gen) {}
        }
    }
    __syncthreads();
}

// ---------------- prologue ----------------
__device__ __forceinline__ void conv_range(const float* __restrict__ src,
                                           __nv_bfloat16* __restrict__ hi,
                                           __nv_bfloat16* __restrict__ lo,
                                           int n_src, int relblk) {
    int i = (relblk * 256 + threadIdx.x) * 4;
    float4 v = make_float4(0.f, 0.f, 0.f, 0.f);
    if (i < n_src) v = *(const float4*)(src + i);
    __nv_bfloat16 h0 = __float2bfloat16(v.x), h1 = __float2bfloat16(v.y);
    __nv_bfloat16 h2 = __float2bfloat16(v.z), h3 = __float2bfloat16(v.w);
    ((__nv_bfloat162*)(hi + i))[0] = __halves2bfloat162(h0, h1);
    ((__nv_bfloat162*)(hi + i))[1] = __halves2bfloat162(h2, h3);
    ((__nv_bfloat162*)(lo + i))[0] = __halves2bfloat162(
        __float2bfloat16(v.x - __bfloat162float(h0)), __float2bfloat16(v.y - __bfloat162float(h1)));
    ((__nv_bfloat162*)(lo + i))[1] = __halves2bfloat162(
        __float2bfloat16(v.z - __bfloat162float(h2)), __float2bfloat16(v.w - __bfloat162float(h3)));
}

#define PB_EMBED  64
#define PB_CF     2112
#define PB_CAR    8384
#define PB_CW1    11456
#define PB_CW2    11712
#define PB_CWIH   12096
#define PB_CWG    13120
#define PB_CWF    16704
#define PB_TOTAL  31704

__global__ void prologue(const float* __restrict__ features, const float* __restrict__ articles,
                         const float* __restrict__ emb, const int* __restrict__ captions,
                         const float* __restrict__ ihw, const float* __restrict__ ihb,
                         const float* __restrict__ icw, const float* __restrict__ icb,
                         const float* __restrict__ attUw, const float* __restrict__ paUw,
                         const float* __restrict__ w_ih, const float* __restrict__ w_hh,
                         const float* __restrict__ fcnw) {
    int blk = blockIdx.x, tid = threadIdx.x;
    if (blk < PB_EMBED) {
        __shared__ float x[1280];
        int b = blk, lane = tid & 31, wid = tid >> 5;
        for (int k = tid; k < ENC; k += 256) {
            float s = 0.f;
            const float* p = features + (size_t)b * NF * ENC + k;
            for (int n = 0; n < NF; n++) s += p[n * ENC];
            x[k] = s * (1.f / NF);
        }
        for (int k = tid; k < BENC; k += 256) {
            float s = 0.f;
            const float* p = articles + (size_t)b * NP * BENC + k;
            for (int n = 0; n < NP; n++) s += p[n * BENC];
            x[ENC + k] = s * (1.f / NP);
        }
        __syncthreads();
        for (int d = wid; d < Dz; d += 8) {
            float sh = 0.f, sc = 0.f;
            const float* hr = ihw + (size_t)d * 1280;
            const float* cr = icw + (size_t)d * 1280;
            for (int k = lane; k < 1280; k += 32) { float xv = x[k]; sh += hr[k] * xv; sc += cr[k] * xv; }
#pragma unroll
            for (int o = 16; o; o >>= 1) {
                sh += __shfl_xor_sync(0xffffffffu, sh, o);
                sc += __shfl_xor_sync(0xffffffffu, sc, o);
            }
            if (!lane) {
                float h0 = sh + ihb[d];
                g_h[b * Dz + d] = h0;
                g_c[b * Dz + d] = sc + icb[d];
                split_store(g_xhi, g_xlo, (size_t)b * KP + 1280 + d, h0);
            }
        }
    } else if (blk < PB_CF) {
        int bs = blk - PB_EMBED;
        int cap = captions[bs];
        const float* e = emb + (size_t)cap * Ez;
        for (int k = tid; k < Ez; k += 256)
            split_store(g_ehi, g_elo, (size_t)bs * Ez + k, e[k]);
    } else if (blk < PB_CAR) {
        conv_range(features, g_fhi, g_flo, Bz * NF * ENC, blk - PB_CF);
    } else if (blk < PB_CW1) {
        conv_range(articles, g_arhi, g_arlo, Bz * NP * BENC, blk - PB_CAR);
    } else if (blk < PB_CW2) {
        conv_range(attUw, g_w1hi, g_w1lo, Az * ENC, blk - PB_CW1);
    } else if (blk < PB_CWIH) {
        conv_range(paUw, g_w2hi, g_w2lo, Az * BENC, blk - PB_CW2);
    } else if (blk < PB_CWG) {
        // packed w_ih[:, :512] (emb part for precomputed gemb GEMM)
        int i = ((blk - PB_CWIH) * 256 + tid) * 4;
        int row = i >> 9, col = i & 511;
        float4 v = *(const float4*)(w_ih + (size_t)row * 1792 + col);
        __nv_bfloat16 h0 = __float2bfloat16(v.x), h1 = __float2bfloat16(v.y);
        __nv_bfloat16 h2 = __float2bfloat16(v.z), h3 = __float2bfloat16(v.w);
        ((__nv_bfloat162*)(g_wsehi + i))[0] = __halves2bfloat162(h0, h1);
        ((__nv_bfloat162*)(g_wsehi + i))[1] = __halves2bfloat162(h2, h3);
        ((__nv_bfloat162*)(g_wselo + i))[0] = __halves2bfloat162(
            __float2bfloat16(v.x - __bfloat162float(h0)), __float2bfloat16(v.y - __bfloat162float(h1)));
        ((__nv_bfloat162*)(g_wselo + i))[1] = __halves2bfloat162(
            __float2bfloat16(v.z - __bfloat162float(h2)), __float2bfloat16(v.w - __bfloat162float(h3)));
    } else if (blk < PB_CWF) {
        // packed gates W: [ctx | pctx | h] = w_ih[:,512:1792] | w_hh
        int i = ((blk - PB_CWG) * 256 + tid) * 4;
        int j = i / KP, col = i % KP;
        const float* src = (col < 1280) ? (w_ih + (size_t)j * 1792 + 512 + col)
                                        : (w_hh + (size_t)j * 512 + (col - 1280));
        float4 v = *(const float4*)src;
        __nv_bfloat16 h0 = __float2bfloat16(v.x), h1 = __float2bfloat16(v.y);
        __nv_bfloat16 h2 = __float2bfloat16(v.z), h3 = __float2bfloat16(v.w);
        ((__nv_bfloat162*)(g_wghi + i))[0] = __halves2bfloat162(h0, h1);
        ((__nv_bfloat162*)(g_wghi + i))[1] = __halves2bfloat162(h2, h3);
        ((__nv_bfloat162*)(g_wglo + i))[0] = __halves2bfloat162(
            __float2bfloat16(v.x - __bfloat162float(h0)), __float2bfloat16(v.y - __bfloat162float(h1)));
        ((__nv_bfloat162*)(g_wglo + i))[1] = __halves2bfloat162(
            __float2bfloat16(v.z - __bfloat162float(h2)), __float2bfloat16(v.w - __bfloat162float(h3)));
    } else {
        conv_range(fcnw, g_whi, g_wlo, Vz * Dz, blk - PB_CWF);
    }
}

// -------- split-bf16 mma.sync GEMM tile (ldmatrix feed) --------
__device__ __forceinline__ void gemm_tile(
        const __nv_bfloat16* __restrict__ Ahi, const __nv_bfloat16* __restrict__ Alo,
        const __nv_bfloat16* __restrict__ Whi, const __nv_bfloat16* __restrict__ Wlo,
        const float* __restrict__ bias, float* __restrict__ C, int N, int K,
        int m0, int n0, bool perm) {
    __shared__ __align__(16) char smA[2][8192];
    __shared__ __align__(16) char smW[2][8192];
    const int tid = threadIdx.x, lane = tid & 31, wid = tid >> 5;
    const int wm = wid & 1, wn = wid >> 1;
    const int lr4 = lane >> 2, lw = lane & 3;
    const int t8 = lane >> 3, rw = lane & 7;
    const int kc = K >> 5, nch = 3 * kc;
    const int r1 = tid >> 2, cA = tid & 3;
    const uint32_t so1 = swz(r1, cA), so2 = swz(r1 + 64, cA);
    const uint32_t sa[2] = { smem_u32(smA[0]), smem_u32(smA[1]) };
    const uint32_t sb[2] = { smem_u32(smW[0]), smem_u32(smW[1]) };
    float acc[4][4][4] = {};

#define ISSUE(cc, st) do {                                                     \
        int part = ((cc) >= 2 * kc) ? 2 : ((cc) >= kc ? 1 : 0);                \
        int kk = ((cc) - part * kc) << 5;                                      \
        const __nv_bfloat16* As = (part == 1) ? Alo : Ahi;                     \
        const __nv_bfloat16* Ws = (part == 2) ? Wlo : Whi;                     \
        cpa16(sa[st] + so1, As + (size_t)(m0 + r1) * K + kk + cA * 8);         \
        cpa16(sa[st] + so2, As + (size_t)(m0 + r1 + 64) * K + kk + cA * 8);    \
        cpa16(sb[st] + so1, Ws + (size_t)(n0 + r1) * K + kk + cA * 8);         \
        cpa16(sb[st] + so2, Ws + (size_t)(n0 + r1 + 64) * K + kk + cA * 8);    \
        asm volatile("cp.async.commit_group;" ::: "memory");                   \
    } while (0)

    ISSUE(0, 0);
    for (int cc = 0; cc < nch; cc++) {
        const int st = cc & 1;
        if (cc + 1 < nch) {
            ISSUE(cc + 1, st ^ 1);
            asm volatile("cp.async.wait_group 1;" ::: "memory");
        } else {
            asm volatile("cp.async.wait_group 0;" ::: "memory");
        }
        __syncthreads();
        const uint32_t saSt = sa[st], sbSt = sb[st];
#pragma unroll
        for (int ks = 0; ks < 2; ks++) {
            uint32_t bf[4][2];
#pragma unroll
            for (int nip = 0; nip < 2; nip++) {
                uint32_t r0, r1b, r2, r3;
                ldsm4(r0, r1b, r2, r3,
                      sbSt + swz(wn * 32 + nip * 16 + ((t8 >> 1) << 3) + rw, 2 * ks + (t8 & 1)));
                bf[nip * 2][0] = r0; bf[nip * 2][1] = r1b;
                bf[nip * 2 + 1][0] = r2; bf[nip * 2 + 1][1] = r3;
            }
#pragma unroll
            for (int mi = 0; mi < 4; mi++) {
                uint32_t a0, a1, a2, a3;
                ldsm4(a0, a1, a2, a3,
                      saSt + swz(wm * 64 + mi * 16 + ((t8 & 1) << 3) + rw, 2 * ks + (t8 >> 1)));
#pragma unroll
                for (int ni = 0; ni < 4; ni++)
                    mma16816(acc[mi][ni], a0, a1, a2, a3, bf[ni][0], bf[ni][1]);
            }
        }
        __syncthreads();
    }
#undef ISSUE
#pragma unroll
    for (int mi = 0; mi < 4; mi++) {
#pragma unroll
        for (int ni = 0; ni < 4; ni++) {
            int m = m0 + wm * 64 + mi * 16 + lr4;
            int n = n0 + wn * 32 + ni * 8 + lw * 2;
            if (n < N) {
                float bx = bias[n], by = bias[n + 1];
                size_t row0 = perm ? (size_t)((m & 63) * Sz + (m >> 6)) * N : (size_t)m * N;
                size_t row1 = perm ? (size_t)(((m + 8) & 63) * Sz + ((m + 8) >> 6)) * N
                                   : (size_t)(m + 8) * N;
                *(float2*)(C + row0 + n) = make_float2(acc[mi][ni][0] + bx, acc[mi][ni][1] + by);
                *(float2*)(C + row1 + n) = make_float2(acc[mi][ni][2] + bx, acc[mi][ni][3] + by);
            }
        }
    }
}

__global__ void __launch_bounds__(256)
gemm3(const float* __restrict__ attUb, const float* __restrict__ paUb) {
    int y = blockIdx.y, x = blockIdx.x;
    if (y < 98) {
        if (x >= 4) return;
        gemm_tile(g_fhi, g_flo, g_w1hi, g_w1lo, attUb, g_u_feat, Az, ENC, y * 128, x * 128, false);
    } else if (y < 130) {
        if (x >= 4) return;
        gemm_tile(g_arhi, g_arlo, g_w2hi, g_w2lo, paUb, g_u_art, Az, BENC, (y - 98) * 128, x * 128, false);
    } else {
        gemm_tile(g_ehi, g_elo, g_wsehi, g_wselo, g_zbias, g_gemb, G4, 512, (y - 130) * 128, x * 128, false);
    }
}

__global__ void __launch_bounds__(256)
gemm_fcn(const float* __restrict__ bias, float* __restrict__ C) {
    gemm_tile(g_ahi, g_alo, g_whi, g_wlo, bias, C, Vz, Dz,
              blockIdx.y * 128, blockIdx.x * 128, true);
}

// ---------------- persistent loop ----------------
__device__ __forceinline__ void attend_p(float* sh, const float* __restrict__ F,
                                         const float* __restrict__ u,
                                         const float* __restrict__ Aw, float Ab,
                                         int type, int b, int Nn, int Kd, int xoff,
                                         float* __restrict__ outp) {
    const int tid = threadIdx.x, lane = tid & 31, wid = tid >> 5;
    float* wahs = sh;
    float* aws  = sh + 512;
    float* sc   = sh + 1024;
    float* red  = sh + 1232;
    float* sm   = sh + 1248;

    wahs[tid] = g_wah[(size_t)(type * Bz + b) * Az + tid];
    aws[tid] = Aw[tid];
    __syncthreads();

    const float4* w4 = (const float4*)wahs;
    const float4* a4p = (const float4*)aws;
    for (int n = wid; n < Nn; n += 16) {
        const float4* ur4 = (const float4*)(u + (size_t)n * Az);
        float s = 0.f;
#pragma unroll
        for (int q = 0; q < 4; q++) {
            int idx = lane + q * 32;
            float4 uu = ur4[idx];
            float4 ww = w4[idx];
            float4 aa = a4p[idx];
            s += tanha(uu.x + ww.x) * aa.x + tanha(uu.y + ww.y) * aa.y +
                 tanha(uu.z + ww.z) * aa.z + tanha(uu.w + ww.w) * aa.w;
        }
        s = wred(s);
        if (!lane) sc[n] = s + Ab;
    }
    __syncthreads();

    float m = -1e30f;
    for (int n = tid; n < Nn; n += LT) m = fmaxf(m, sc[n]);
#pragma unroll
    for (int o = 16; o; o >>= 1) m = fmaxf(m, __shfl_xor_sync(0xffffffffu, m, o));
    if (!lane) red[wid] = m;
    __syncthreads();
    if (tid == 0) {
        float mm = red[0];
        for (int i = 1; i < 16; i++) mm = fmaxf(mm, red[i]);
        sm[0] = mm;
    }
    __syncthreads();
    float e = 0.f;
    for (int n = tid; n < Nn; n += LT) { float ex = expf(sc[n] - sm[0]); sc[n] = ex; e += ex; }
    e = wred(e);
    if (!lane) red[wid] = e;
    __syncthreads();
    if (tid == 0) {
        float ss = 0.f;
        for (int i = 0; i < 16; i++) ss += red[i];
        sm[1] = ss;
    }
    __syncthreads();
    const float inv = 1.f / sm[1];
    for (int n = tid; n < Nn; n += LT) { float al = sc[n] * inv; sc[n] = al; outp[n] = al; }
    __syncthreads();

    // ctx: thread owns 4 k's (float4 loads); write split-bf16 into X
    int k4 = tid * 4;
    if (k4 < Kd) {
        float a0 = 0.f, a1 = 0.f, a2 = 0.f, a3 = 0.f;
        const float* Fk = F + k4;
        for (int n = 0; n < Nn; n++) {
            float4 f = *(const float4*)(Fk + (size_t)n * Kd);
            float al = sc[n];
            a0 += al * f.x; a1 += al * f.y; a2 += al * f.z; a3 += al * f.w;
        }
        size_t base = (size_t)b * KP + xoff + k4;
        __nv_bfloat16 h0 = __float2bfloat16(a0), h1 = __float2bfloat16(a1);
        __nv_bfloat16 h2 = __float2bfloat16(a2), h3 = __float2bfloat16(a3);
        ((__nv_bfloat162*)(g_xhi + base))[0] = __halves2bfloat162(h0, h1);
        ((__nv_bfloat162*)(g_xhi + base))[1] = __halves2bfloat162(h2, h3);
        ((__nv_bfloat162*)(g_xlo + base))[0] = __halves2bfloat162(
            __float2bfloat16(a0 - __bfloat162float(h0)), __float2bfloat16(a1 - __bfloat162float(h1)));
        ((__nv_bfloat162*)(g_xlo + base))[1] = __halves2bfloat162(
            __float2bfloat16(a2 - __bfloat162float(h2)), __float2bfloat16(a3 - __bfloat162float(h3)));
    }
}

// tensor-core gates: block = (nt, ks): 64 x 128 tile over K-split of 224 (x3 parts)
__device__ __forceinline__ void gates_mma(float* sh, int nt, int ks) {
    const int tid = threadIdx.x, lane = tid & 31, wid = tid >> 5;
    const int wn = wid & 7, mh = wid >> 3;
    const int lr4 = lane >> 2, lw = lane & 3;
    const int t8 = lane >> 3, rw = lane & 7;
    const int koff = ks * 224;
    // smem: X[2][64x64B] at 0 / 4KB ; W[2][128x64B] at 8KB / 16KB
    char* smem = (char*)sh;
    const uint32_t sx[2] = { smem_u32(smem), smem_u32(smem + 4096) };
    const uint32_t sw[2] = { smem_u32(smem + 8192), smem_u32(smem + 16384) };
    const int xr = tid >> 2, xq = tid & 3;   // X: tid<256 (r 0-63); W: all (r 0-127)
    float acc[2][2][4] = {};

#define GISS(cc, st) do {                                                          \
        int part = (cc) / 7;                                                       \
        int kk = koff + ((cc) % 7) * 32;                                           \
        const __nv_bfloat16* Xs_ = (part == 1) ? g_xlo : g_xhi;                    \
        const __nv_bfloat16* Ws_ = (part == 2) ? g_wglo : g_wghi;                  \
        if (tid < 256) cpa16(sx[st] + swz(xr, xq), Xs_ + (size_t)xr * KP + kk + xq * 8); \
        cpa16(sw[st] + swz(xr & 127, xq), Ws_ + (size_t)(nt * 128 + (xr & 127)) * KP + kk + xq * 8); \
        asm volatile("cp.async.commit_group;" ::: "memory");                       \
    } while (0)

    GISS(0, 0);
    for (int cc = 0; cc < 21; cc++) {
        const int st = cc & 1;
        if (cc + 1 < 21) {
            GISS(cc + 1, st ^ 1);
            asm volatile("cp.async.wait_group 1;" ::: "memory");
        } else {
            asm volatile("cp.async.wait_group 0;" ::: "memory");
        }
        __syncthreads();
        const uint32_t sxSt = sx[st], swSt = sw[st];
#pragma unroll
        for (int ks2 = 0; ks2 < 2; ks2++) {
            uint32_t b0, b1, b2, b3;
            ldsm4(b0, b1, b2, b3,
                  swSt + swz(wn * 16 + ((t8 >> 1) << 3) + rw, 2 * ks2 + (t8 & 1)));
#pragma unroll
            for (int mi = 0; mi < 2; mi++) {
                uint32_t a0, a1, a2, a3;
                ldsm4(a0, a1, a2, a3,
                      sxSt + swz(mh * 32 + mi * 16 + ((t8 & 1) << 3) + rw, 2 * ks2 + (t8 >> 1)));
                mma16816(acc[mi][0], a0, a1, a2, a3, b0, b1);
                mma16816(acc[mi][1], a0, a1, a2, a3, b2, b3);
            }
        }
        __syncthreads();
    }
#undef GISS
#pragma unroll
    for (int mi = 0; mi < 2; mi++) {
#pragma unroll
        for (int ni = 0; ni < 2; ni++) {
            int m = mh * 32 + mi * 16 + lr4;
            int n = nt * 128 + wn * 16 + ni * 8 + lw * 2;
            *(float2*)(g_gparts8 + ((size_t)ks * Bz + m) * G4 + n) =
                make_float2(acc[mi][ni][0], acc[mi][ni][1]);
            *(float2*)(g_gparts8 + ((size_t)ks * Bz + m + 8) * G4 + n) =
                make_float2(acc[mi][ni][2], acc[mi][ni][3]);
        }
    }
}

__global__ void __launch_bounds__(LT)
loop_kernel(const float* __restrict__ features, const float* __restrict__ articles,
            const float* __restrict__ attWw, const float* __restrict__ attWb,
            const float* __restrict__ attAw, const float* __restrict__ attAb,
            const float* __restrict__ paWw, const float* __restrict__ paWb,
            const float* __restrict__ paAw, const float* __restrict__ paAb,
            const float* __restrict__ b_ih, const float* __restrict__ b_hh,
            float* __restrict__ out) {
    __shared__ __align__(16) float sh[6144];   // 24KB
    const int bid = blockIdx.x, tid = threadIdx.x;
    const int lane = tid & 31, wid = tid >> 5;
    const int type = bid >> 6, b = bid & 63;
    const float* Wt = type ? paWw : attWw;
    const float* Wbv = type ? paWb : attWb;

    for (int t = 0; t < Sz; t++) {
        // ---- A: distributed wah (rows [b*8, b*8+8) for all 64 batches)
        {
            const int a0 = b * 8;
            for (int i = tid; i < 1024; i += LT)
                ((float4*)sh)[i] = *(const float4*)(Wt + (size_t)(a0 + (i >> 7)) * Dz + ((i & 127) << 2));
            __syncthreads();
#pragma unroll 1
            for (int ib = 0; ib < 4; ib++) {
                int b2 = wid + ib * 16;
                const float4* hp = (const float4*)(g_h + b2 * Dz);
                float4 h4[4];
#pragma unroll
                for (int q = 0; q < 4; q++) h4[q] = hp[lane + q * 32];
#pragma unroll 1
                for (int r = 0; r < 8; r++) {
                    const float4* wr4 = (const float4*)(sh + r * 512);
                    float s = 0.f;
#pragma unroll
                    for (int q = 0; q < 4; q++) {
                        float4 wv = wr4[lane + q * 32];
                        s += wv.x * h4[q].x + wv.y * h4[q].y + wv.z * h4[q].z + wv.w * h4[q].w;
                    }
                    s = wred(s);
                    if (!lane) g_wah[(size_t)(type * Bz + b2) * Az + a0 + r] = s + Wbv[a0 + r];
                }
            }
        }
        gbar();
        // ---- B: attention; ctx/pctx written as split-bf16 into X
        if (type == 0)
            attend_p(sh, features + (size_t)b * NF * ENC, g_u_feat + (size_t)b * NF * Az,
                     attAw, attAb[0], 0, b, NF, ENC, 0,
                     out + OFF_ALPHA + (size_t)(b * Sz + t) * NF);
        else
            attend_p(sh, articles + (size_t)b * NP * BENC, g_u_art + (size_t)b * NP * Az,
                     paAw, paAb[0], 1, b, NP, BENC, 512,
                     out + OFF_PA + (size_t)(b * Sz + t) * NP);
        gbar();
        // ---- C: tensor-core gates (all 128 blocks; 16 n-tiles x 8 k-splits)
        gates_mma(sh, bid & 15, bid >> 4);
        gbar();
        // ---- D: LSTM pointwise (type0 blocks)
        if (type == 0) {
            int d = tid;
            const float* ge = g_gemb + (size_t)(b * Sz + t) * G4;
            float gi = b_ih[d] + b_hh[d] + ge[d];
            float gf = b_ih[512 + d] + b_hh[512 + d] + ge[512 + d];
            float gg = b_ih[1024 + d] + b_hh[1024 + d] + ge[1024 + d];
            float go = b_ih[1536 + d] + b_hh[1536 + d] + ge[1536 + d];
#pragma unroll
            for (int ks = 0; ks < 8; ks++) {
                const float* gp = g_gparts8 + ((size_t)ks * Bz + b) * G4;
                gi += gp[d]; gf += gp[512 + d]; gg += gp[1024 + d]; go += gp[1536 + d];
            }
            float cp = g_c[b * Dz + d];
            float cn = sigm(gf) * cp + sigm(gi) * tanhf(gg);
            float hn = sigm(go) * tanhf(cn);
            g_c[b * Dz + d] = cn;
            g_h[b * Dz + d] = hn;
            __nv_bfloat16 hh = __float2bfloat16(hn);
            __nv_bfloat16 hl = __float2bfloat16(hn - __bfloat162float(hh));
            size_t idx = ((size_t)t * Bz + b) * Dz + d;
            g_ahi[idx] = hh;
            g_alo[idx] = hl;
            g_xhi[(size_t)b * KP + 1280 + d] = hh;
            g_xlo[(size_t)b * KP + 1280 + d] = hl;
        }
        gbar();
    }
}

// ---------------- launcher: 4 launches; #4 = gemm_fcn (ncu target) ----------------
extern "C" void kernel_launch(void* const* d_in, const int* in_sizes, int n_in,
                              void* d_out, int out_size) {
    const float* features = (const float*)d_in[0];
    const float* articles = (const float*)d_in[1];
    const int*   captions = (const int*)d_in[2];
    const float* emb      = (const float*)d_in[3];
    const float* att_W_w  = (const float*)d_in[4];
    const float* att_W_b  = (const float*)d_in[5];
    const float* att_U_w  = (const float*)d_in[6];
    const float* att_U_b  = (const float*)d_in[7];
    const float* att_A_w  = (const float*)d_in[8];
    const float* att_A_b  = (const float*)d_in[9];
    const float* pa_W_w   = (const float*)d_in[10];
    const float* pa_W_b   = (const float*)d_in[11];
    const float* pa_U_w   = (const float*)d_in[12];
    const float* pa_U_b   = (const float*)d_in[13];
    const float* pa_A_w   = (const float*)d_in[14];
    const float* pa_A_b   = (const float*)d_in[15];
    const float* init_h_w = (const float*)d_in[16];
    const float* init_h_b = (const float*)d_in[17];
    const float* init_c_w = (const float*)d_in[18];
    const float* init_c_b = (const float*)d_in[19];
    const float* lstm_w_ih = (const float*)d_in[20];
    const float* lstm_w_hh = (const float*)d_in[21];
    const float* lstm_b_ih = (const float*)d_in[22];
    const float* lstm_b_hh = (const float*)d_in[23];
    const float* fcn_w    = (const float*)d_in[24];
    const float* fcn_b    = (const float*)d_in[25];
    float* out = (float*)d_out;

    prologue<<<PB_TOTAL, 256>>>(features, articles, emb, captions,
                                init_h_w, init_h_b, init_c_w, init_c_b,
                                att_U_w, pa_U_w, lstm_w_ih, lstm_w_hh, fcn_w);
    gemm3<<<dim3(16, 146), 256>>>(att_U_b, pa_U_b);
    loop_kernel<<<NBLK, LT>>>(features, articles,
                              att_W_w, att_W_b, att_A_w, att_A_b,
                              pa_W_w, pa_W_b, pa_A_w, pa_A_b,
                              lstm_b_ih, lstm_b_hh, out);
    gemm_fcn<<<dim3(236, 16), 256>>>(fcn_b, out);
}